// round 1
// baseline (speedup 1.0000x reference)
#include <cuda_runtime.h>
#include <math.h>

#define NN 100000
#define EE 1200000
#define CC 64
#define TOTE (EE + NN)

// ---------------- scratch (device globals; no allocation allowed) ----------------
__device__ float g_h0a[NN * CC];   // leaky(x@W1+b1)
__device__ float g_h0r[NN * CC];   // leaky(rg_x@W1+b1)
__device__ float g_hW[NN * CC];    // per-conv h@W (reused sequentially)
__device__ float g_atom[NN * CC];  // atom conv output
__device__ float g_rh[NN * CC];    // rg conv output
__device__ float g_mol[NN * CC];   // mol conv output
__device__ float g_as[NN];
__device__ float g_ad[NN];

__device__ int g_degA[NN];
__device__ int g_offA[NN + 1];
__device__ int g_curA[NN];
__device__ int g_csrA[TOTE];

__device__ int g_degR[NN];
__device__ int g_offR[NN + 1];
__device__ int g_curR[NN];
__device__ int g_csrR[TOTE];

// ---------------- GEMM: out[n,64] = act(A[n,64] @ W[64,64] + bias) ----------------
__global__ void gemm64_kernel(const float* __restrict__ A, const float* __restrict__ W,
                              const float* __restrict__ bias, float* __restrict__ out,
                              int n, float slope, int use_act) {
    __shared__ float As[64][68];
    __shared__ float Ws[64][68];
    int tid = threadIdx.x;           // 256 threads
    int row0 = blockIdx.x * 64;

    for (int i = tid; i < 64 * 64; i += 256) {
        Ws[i >> 6][i & 63] = W[i];
    }
    for (int i = tid; i < 64 * 64; i += 256) {
        int r = i >> 6, c = i & 63;
        As[r][c] = (row0 + r < n) ? A[(row0 + r) * 64 + c] : 0.f;
    }
    __syncthreads();

    int rg = (tid >> 4) * 4;
    int cg = (tid & 15) * 4;
    float acc[4][4];
#pragma unroll
    for (int i = 0; i < 4; i++)
#pragma unroll
        for (int j = 0; j < 4; j++) acc[i][j] = 0.f;

#pragma unroll
    for (int k = 0; k < 64; k++) {
        float a[4], w[4];
#pragma unroll
        for (int i = 0; i < 4; i++) a[i] = As[rg + i][k];
#pragma unroll
        for (int j = 0; j < 4; j++) w[j] = Ws[k][cg + j];
#pragma unroll
        for (int i = 0; i < 4; i++)
#pragma unroll
            for (int j = 0; j < 4; j++) acc[i][j] += a[i] * w[j];
    }

#pragma unroll
    for (int i = 0; i < 4; i++) {
        int row = row0 + rg + i;
        if (row < n) {
#pragma unroll
            for (int j = 0; j < 4; j++) {
                int c = cg + j;
                float v = acc[i][j] + (bias ? bias[c] : 0.f);
                if (use_act) v = (v >= 0.f) ? v : slope * v;
                out[row * 64 + c] = v;
            }
        }
    }
}

// out[n,64] = concat(A1,A2)[n,128] @ W2[128,64] + b2
__global__ void gemm_concat_kernel(const float* __restrict__ A1, const float* __restrict__ A2,
                                   const float* __restrict__ W2, const float* __restrict__ b2,
                                   float* __restrict__ out, int n) {
    __shared__ float As[64][68];
    __shared__ float Ws[64][68];
    int tid = threadIdx.x;
    int row0 = blockIdx.x * 64;
    int rg = (tid >> 4) * 4;
    int cg = (tid & 15) * 4;
    float acc[4][4];
#pragma unroll
    for (int i = 0; i < 4; i++)
#pragma unroll
        for (int j = 0; j < 4; j++) acc[i][j] = 0.f;

    for (int phase = 0; phase < 2; phase++) {
        const float* A = phase ? A2 : A1;
        const float* Wp = W2 + phase * 64 * 64;
        if (phase) __syncthreads();
        for (int i = tid; i < 64 * 64; i += 256) Ws[i >> 6][i & 63] = Wp[i];
        for (int i = tid; i < 64 * 64; i += 256) {
            int r = i >> 6, c = i & 63;
            As[r][c] = (row0 + r < n) ? A[(row0 + r) * 64 + c] : 0.f;
        }
        __syncthreads();
#pragma unroll
        for (int k = 0; k < 64; k++) {
            float a[4], w[4];
#pragma unroll
            for (int i = 0; i < 4; i++) a[i] = As[rg + i][k];
#pragma unroll
            for (int j = 0; j < 4; j++) w[j] = Ws[k][cg + j];
#pragma unroll
            for (int i = 0; i < 4; i++)
#pragma unroll
                for (int j = 0; j < 4; j++) acc[i][j] += a[i] * w[j];
        }
    }

#pragma unroll
    for (int i = 0; i < 4; i++) {
        int row = row0 + rg + i;
        if (row < n) {
#pragma unroll
            for (int j = 0; j < 4; j++) {
                int c = cg + j;
                out[row * 64 + c] = acc[i][j] + b2[c];
            }
        }
    }
}

// ---------------- attention scalars: a_s[i]=hW[i,:]@att_src, a_d likewise ----------------
__global__ void att_kernel(const float* __restrict__ hW, const float* __restrict__ att_src,
                           const float* __restrict__ att_dst, float* __restrict__ as_,
                           float* __restrict__ ad_, int n) {
    int warp = (blockIdx.x * blockDim.x + threadIdx.x) >> 5;
    int lane = threadIdx.x & 31;
    if (warp >= n) return;
    float v0 = hW[warp * 64 + lane];
    float v1 = hW[warp * 64 + 32 + lane];
    float s = v0 * att_src[lane] + v1 * att_src[32 + lane];
    float d = v0 * att_dst[lane] + v1 * att_dst[32 + lane];
#pragma unroll
    for (int o = 16; o; o >>= 1) {
        s += __shfl_xor_sync(0xffffffffu, s, o);
        d += __shfl_xor_sync(0xffffffffu, d, o);
    }
    if (lane == 0) {
        as_[warp] = s;
        ad_[warp] = d;
    }
}

// ---------------- CSR build ----------------
__global__ void init_deg_kernel(int* deg, int n) {
    int i = blockIdx.x * blockDim.x + threadIdx.x;
    if (i < n) deg[i] = 1;  // self loop
}
__global__ void count_kernel(const int* __restrict__ dst, int* __restrict__ deg, int e) {
    int i = blockIdx.x * blockDim.x + threadIdx.x;
    if (i < e) atomicAdd(&deg[dst[i]], 1);
}
// single block of 1024 threads, grid-stride exclusive scan with carry
__global__ void scan_kernel(const int* __restrict__ deg, int* __restrict__ off, int n) {
    __shared__ int sh[1024];
    int tid = threadIdx.x;
    int carry = 0;
    for (int base = 0; base < n; base += 1024) {
        int i = base + tid;
        int v = (i < n) ? deg[i] : 0;
        sh[tid] = v;
        __syncthreads();
        for (int o = 1; o < 1024; o <<= 1) {
            int t = (tid >= o) ? sh[tid - o] : 0;
            __syncthreads();
            sh[tid] += t;
            __syncthreads();
        }
        if (i < n) off[i] = carry + sh[tid] - v;
        int tot = sh[1023];
        carry += tot;
        __syncthreads();
    }
    if (tid == 0) off[n] = carry;
}
__global__ void fill_self_kernel(const int* __restrict__ off, int* __restrict__ cursor,
                                 int* __restrict__ csr, int n) {
    int i = blockIdx.x * blockDim.x + threadIdx.x;
    if (i < n) {
        int o = off[i];
        csr[o] = i;          // self loop occupies slot 0 of the segment
        cursor[i] = o + 1;
    }
}
__global__ void scatter_kernel(const int* __restrict__ src, const int* __restrict__ dst,
                               int* __restrict__ cursor, int* __restrict__ csr, int e) {
    int i = blockIdx.x * blockDim.x + threadIdx.x;
    if (i < e) {
        int p = atomicAdd(&cursor[dst[i]], 1);
        csr[p] = src[i];
    }
}

// ---------------- GAT aggregation: one warp per dst node ----------------
__global__ void gat_aggregate_kernel(const int* __restrict__ off, const int* __restrict__ csr,
                                     const float* __restrict__ hW, const float* __restrict__ as_,
                                     const float* __restrict__ ad_, const float* __restrict__ bias,
                                     float* __restrict__ out, int n) {
    int warp = (blockIdx.x * blockDim.x + threadIdx.x) >> 5;
    int lane = threadIdx.x & 31;
    if (warp >= n) return;
    int start = off[warp];
    int end = off[warp + 1];
    float adi = ad_[warp];

    // pass 1: segment max of leaky(e)
    float m = -1e30f;
    for (int j = start + lane; j < end; j += 32) {
        float e = as_[csr[j]] + adi;
        e = (e >= 0.f) ? e : 0.2f * e;
        m = fmaxf(m, e);
    }
#pragma unroll
    for (int o = 16; o; o >>= 1) m = fmaxf(m, __shfl_xor_sync(0xffffffffu, m, o));

    // pass 2: denom
    float s = 0.f;
    for (int j = start + lane; j < end; j += 32) {
        float e = as_[csr[j]] + adi;
        e = (e >= 0.f) ? e : 0.2f * e;
        s += __expf(e - m);
    }
#pragma unroll
    for (int o = 16; o; o >>= 1) s += __shfl_xor_sync(0xffffffffu, s, o);
    float inv = 1.f / (s + 1e-16f);

    // pass 3: weighted feature sum; lane handles channels (lane, lane+32)
    float acc0 = 0.f, acc1 = 0.f;
    for (int base = start; base < end; base += 32) {
        int j = base + lane;
        int sidx = 0;
        float alpha = 0.f;
        if (j < end) {
            sidx = csr[j];
            float e = as_[sidx] + adi;
            e = (e >= 0.f) ? e : 0.2f * e;
            alpha = __expf(e - m) * inv;
        }
        int cnt = min(32, end - base);
        for (int t = 0; t < cnt; t++) {
            int ss = __shfl_sync(0xffffffffu, sidx, t);
            float al = __shfl_sync(0xffffffffu, alpha, t);
            acc0 += al * hW[ss * 64 + lane];
            acc1 += al * hW[ss * 64 + 32 + lane];
        }
    }
    out[warp * 64 + lane] = acc0 + bias[lane];
    out[warp * 64 + 32 + lane] = acc1 + bias[32 + lane];
}

// ---------------- host launcher ----------------
static void build_csr(const int* src, const int* dst, int* deg, int* off, int* cursor, int* csr) {
    init_deg_kernel<<<(NN + 255) / 256, 256>>>(deg, NN);
    count_kernel<<<(EE + 255) / 256, 256>>>(dst, deg, EE);
    scan_kernel<<<1, 1024>>>(deg, off, NN);
    fill_self_kernel<<<(NN + 255) / 256, 256>>>(off, cursor, csr, NN);
    scatter_kernel<<<(EE + 255) / 256, 256>>>(src, dst, cursor, csr, EE);
}

extern "C" void kernel_launch(void* const* d_in, const int* in_sizes, int n_in,
                              void* d_out, int out_size) {
    const float* x       = (const float*)d_in[0];
    const int*   ei      = (const int*)d_in[1];
    const float* rg_x    = (const float*)d_in[3];
    const int*   rei     = (const int*)d_in[4];
    const float* W1      = (const float*)d_in[6];
    const float* b1      = (const float*)d_in[7];
    const float* atom_W  = (const float*)d_in[8];
    const float* atom_as = (const float*)d_in[9];
    const float* atom_ad = (const float*)d_in[10];
    const float* atom_b  = (const float*)d_in[11];
    const float* rg_W    = (const float*)d_in[12];
    const float* rg_as   = (const float*)d_in[13];
    const float* rg_ad   = (const float*)d_in[14];
    const float* rg_b    = (const float*)d_in[15];
    const float* mol_W   = (const float*)d_in[16];
    const float* mol_as  = (const float*)d_in[17];
    const float* mol_ad  = (const float*)d_in[18];
    const float* mol_b   = (const float*)d_in[19];
    const float* W2      = (const float*)d_in[20];
    const float* b2      = (const float*)d_in[21];
    float* out = (float*)d_out;

    const int* srcA = ei;
    const int* dstA = ei + EE;
    const int* srcR = rei;
    const int* dstR = rei + EE;

    // resolve device-global addresses
    float *h0a, *h0r, *hW, *atomo, *rh, *mol, *as_, *ad_;
    int *degA, *offA, *curA, *csrA, *degR, *offR, *curR, *csrR;
    cudaGetSymbolAddress((void**)&h0a, g_h0a);
    cudaGetSymbolAddress((void**)&h0r, g_h0r);
    cudaGetSymbolAddress((void**)&hW, g_hW);
    cudaGetSymbolAddress((void**)&atomo, g_atom);
    cudaGetSymbolAddress((void**)&rh, g_rh);
    cudaGetSymbolAddress((void**)&mol, g_mol);
    cudaGetSymbolAddress((void**)&as_, g_as);
    cudaGetSymbolAddress((void**)&ad_, g_ad);
    cudaGetSymbolAddress((void**)&degA, g_degA);
    cudaGetSymbolAddress((void**)&offA, g_offA);
    cudaGetSymbolAddress((void**)&curA, g_curA);
    cudaGetSymbolAddress((void**)&csrA, g_csrA);
    cudaGetSymbolAddress((void**)&degR, g_degR);
    cudaGetSymbolAddress((void**)&offR, g_offR);
    cudaGetSymbolAddress((void**)&curR, g_curR);
    cudaGetSymbolAddress((void**)&csrR, g_csrR);

    const int GB = (NN + 63) / 64;           // gemm blocks
    const int WB = (NN * 32 + 255) / 256;    // warp-per-node blocks

    // lin1 for both graphs
    gemm64_kernel<<<GB, 256>>>(x, W1, b1, h0a, NN, 0.01f, 1);
    gemm64_kernel<<<GB, 256>>>(rg_x, W1, b1, h0r, NN, 0.01f, 1);

    // CSR for both graphs
    build_csr(srcA, dstA, degA, offA, curA, csrA);
    build_csr(srcR, dstR, degR, offR, curR, csrR);

    // atom conv: h = gat(h0a)
    gemm64_kernel<<<GB, 256>>>(h0a, atom_W, nullptr, hW, NN, 0.f, 0);
    att_kernel<<<WB, 256>>>(hW, atom_as, atom_ad, as_, ad_, NN);
    gat_aggregate_kernel<<<WB, 256>>>(offA, csrA, hW, as_, ad_, atom_b, atomo, NN);

    // rg conv: rh = gat(h0r)
    gemm64_kernel<<<GB, 256>>>(h0r, rg_W, nullptr, hW, NN, 0.f, 0);
    att_kernel<<<WB, 256>>>(hW, rg_as, rg_ad, as_, ad_, NN);
    gat_aggregate_kernel<<<WB, 256>>>(offR, csrR, hW, as_, ad_, rg_b, rh, NN);

    // mol conv: mol = gat(atom_out) on atom graph
    gemm64_kernel<<<GB, 256>>>(atomo, mol_W, nullptr, hW, NN, 0.f, 0);
    att_kernel<<<WB, 256>>>(hW, mol_as, mol_ad, as_, ad_, NN);
    gat_aggregate_kernel<<<WB, 256>>>(offA, csrA, hW, as_, ad_, mol_b, mol, NN);

    // final: out = concat(mol, rh) @ W2 + b2
    gemm_concat_kernel<<<GB, 256>>>(mol, rh, W2, b2, out, NN);
}

// round 2
// speedup vs baseline: 1.3694x; 1.3694x over previous
#include <cuda_runtime.h>
#include <math.h>

#define NN 100000
#define EE 1200000
#define CC 64
#define TOTE (EE + NN)
#define SCHUNK 1024
#define NB_SCAN ((NN + SCHUNK - 1) / SCHUNK)   // 98

// ---------------- scratch (device globals; no allocation allowed) ----------------
__device__ float g_h0a[NN * CC];
__device__ float g_h0r[NN * CC];
__device__ float g_hW[NN * CC];
__device__ float g_atom[NN * CC];
__device__ float g_rh[NN * CC];
__device__ float g_mol[NN * CC];
__device__ float g_as[NN];
__device__ float g_ad[NN];

__device__ int g_degA[NN];
__device__ int g_offA[NN + 1];
__device__ int g_curA[NN];
__device__ int g_csrA[TOTE];

__device__ int g_degR[NN];
__device__ int g_offR[NN + 1];
__device__ int g_curR[NN];
__device__ int g_csrR[TOTE];

__device__ int g_bsum[128];
__device__ int g_boff[128];

// ---------------- GEMM: out[n,64] = act(A[n,64]@W[64,64] + bias); optional fused att ----------------
__global__ void gemm64_kernel(const float* __restrict__ A, const float* __restrict__ W,
                              const float* __restrict__ bias, float* __restrict__ out,
                              int n, float slope, int use_act,
                              const float* __restrict__ attS, const float* __restrict__ attD,
                              float* __restrict__ as_, float* __restrict__ ad_) {
    __shared__ float As[64][68];
    __shared__ float Ws[64][68];
    __shared__ float sS[64];
    __shared__ float sD[64];
    int tid = threadIdx.x;           // 256 threads
    int row0 = blockIdx.x * 64;

    for (int i = tid; i < 64 * 64; i += 256) Ws[i >> 6][i & 63] = W[i];
    for (int i = tid; i < 64 * 64; i += 256) {
        int r = i >> 6, c = i & 63;
        As[r][c] = (row0 + r < n) ? A[(row0 + r) * 64 + c] : 0.f;
    }
    if (attS && tid < 64) { sS[tid] = 0.f; sD[tid] = 0.f; }
    __syncthreads();

    int rg = (tid >> 4) * 4;
    int cg = (tid & 15) * 4;
    float acc[4][4];
#pragma unroll
    for (int i = 0; i < 4; i++)
#pragma unroll
        for (int j = 0; j < 4; j++) acc[i][j] = 0.f;

#pragma unroll
    for (int k = 0; k < 64; k++) {
        float a[4], w[4];
#pragma unroll
        for (int i = 0; i < 4; i++) a[i] = As[rg + i][k];
#pragma unroll
        for (int j = 0; j < 4; j++) w[j] = Ws[k][cg + j];
#pragma unroll
        for (int i = 0; i < 4; i++)
#pragma unroll
            for (int j = 0; j < 4; j++) acc[i][j] += a[i] * w[j];
    }

#pragma unroll
    for (int i = 0; i < 4; i++) {
        int row = row0 + rg + i;
        if (row < n) {
#pragma unroll
            for (int j = 0; j < 4; j++) {
                int c = cg + j;
                float v = acc[i][j] + (bias ? bias[c] : 0.f);
                if (use_act) v = (v >= 0.f) ? v : slope * v;
                out[row * 64 + c] = v;
            }
        }
    }

    // fused attention scalars: as_[row] = hW[row,:]@attS, ad_ likewise
    if (attS) {
        float aS[4], aD[4];
#pragma unroll
        for (int j = 0; j < 4; j++) { aS[j] = attS[cg + j]; aD[j] = attD[cg + j]; }
#pragma unroll
        for (int i = 0; i < 4; i++) {
            float ps = 0.f, pd = 0.f;
#pragma unroll
            for (int j = 0; j < 4; j++) { ps += acc[i][j] * aS[j]; pd += acc[i][j] * aD[j]; }
            atomicAdd(&sS[rg + i], ps);
            atomicAdd(&sD[rg + i], pd);
        }
        __syncthreads();
        if (tid < 64 && row0 + tid < n) {
            as_[row0 + tid] = sS[tid];
            ad_[row0 + tid] = sD[tid];
        }
    }
}

// out[n,64] = concat(A1,A2)[n,128] @ W2[128,64] + b2
__global__ void gemm_concat_kernel(const float* __restrict__ A1, const float* __restrict__ A2,
                                   const float* __restrict__ W2, const float* __restrict__ b2,
                                   float* __restrict__ out, int n) {
    __shared__ float As[64][68];
    __shared__ float Ws[64][68];
    int tid = threadIdx.x;
    int row0 = blockIdx.x * 64;
    int rg = (tid >> 4) * 4;
    int cg = (tid & 15) * 4;
    float acc[4][4];
#pragma unroll
    for (int i = 0; i < 4; i++)
#pragma unroll
        for (int j = 0; j < 4; j++) acc[i][j] = 0.f;

    for (int phase = 0; phase < 2; phase++) {
        const float* A = phase ? A2 : A1;
        const float* Wp = W2 + phase * 64 * 64;
        if (phase) __syncthreads();
        for (int i = tid; i < 64 * 64; i += 256) Ws[i >> 6][i & 63] = Wp[i];
        for (int i = tid; i < 64 * 64; i += 256) {
            int r = i >> 6, c = i & 63;
            As[r][c] = (row0 + r < n) ? A[(row0 + r) * 64 + c] : 0.f;
        }
        __syncthreads();
#pragma unroll
        for (int k = 0; k < 64; k++) {
            float a[4], w[4];
#pragma unroll
            for (int i = 0; i < 4; i++) a[i] = As[rg + i][k];
#pragma unroll
            for (int j = 0; j < 4; j++) w[j] = Ws[k][cg + j];
#pragma unroll
            for (int i = 0; i < 4; i++)
#pragma unroll
                for (int j = 0; j < 4; j++) acc[i][j] += a[i] * w[j];
        }
    }

#pragma unroll
    for (int i = 0; i < 4; i++) {
        int row = row0 + rg + i;
        if (row < n) {
#pragma unroll
            for (int j = 0; j < 4; j++) {
                int c = cg + j;
                out[row * 64 + c] = acc[i][j] + b2[c];
            }
        }
    }
}

// ---------------- CSR build ----------------
__global__ void init_deg_kernel(int* deg, int n) {
    int i = blockIdx.x * blockDim.x + threadIdx.x;
    if (i < n) deg[i] = 1;  // self loop
}
__global__ void count_kernel(const int* __restrict__ dst, int* __restrict__ deg, int e) {
    int i = blockIdx.x * blockDim.x + threadIdx.x;
    if (i < e) atomicAdd(&deg[dst[i]], 1);
}

// 3-kernel multi-block exclusive scan
__global__ void block_sum_kernel(const int* __restrict__ deg, int* __restrict__ bsum, int n) {
    __shared__ int sh[8];
    int base = blockIdx.x * SCHUNK;
    int tid = threadIdx.x;  // 256
    int s = 0;
    for (int i = tid; i < SCHUNK; i += 256) {
        int idx = base + i;
        if (idx < n) s += deg[idx];
    }
#pragma unroll
    for (int o = 16; o; o >>= 1) s += __shfl_xor_sync(0xffffffffu, s, o);
    if ((tid & 31) == 0) sh[tid >> 5] = s;
    __syncthreads();
    if (tid == 0) {
        int t = 0;
#pragma unroll
        for (int k = 0; k < 8; k++) t += sh[k];
        bsum[blockIdx.x] = t;
    }
}
__global__ void scan_sums_kernel(const int* __restrict__ bsum, int* __restrict__ boff,
                                 int nb, int* __restrict__ off, int n) {
    __shared__ int sh[128];
    int tid = threadIdx.x;  // 128
    int v = (tid < nb) ? bsum[tid] : 0;
    sh[tid] = v;
    __syncthreads();
    for (int o = 1; o < 128; o <<= 1) {
        int t = (tid >= o) ? sh[tid - o] : 0;
        __syncthreads();
        sh[tid] += t;
        __syncthreads();
    }
    if (tid < nb) boff[tid] = sh[tid] - v;
    if (tid == 127) off[n] = sh[127];
}
__global__ void scan_apply_kernel(const int* __restrict__ deg, const int* __restrict__ boff,
                                  int* __restrict__ off, int n) {
    __shared__ int wsum[8];
    int tid = threadIdx.x;  // 256, each handles 4 consecutive elems
    int lane = tid & 31, w = tid >> 5;
    int base = blockIdx.x * SCHUNK + tid * 4;
    int v[4];
    int s = 0;
#pragma unroll
    for (int k = 0; k < 4; k++) {
        v[k] = (base + k < n) ? deg[base + k] : 0;
        s += v[k];
    }
    int ps = s;
#pragma unroll
    for (int o = 1; o < 32; o <<= 1) {
        int t = __shfl_up_sync(0xffffffffu, ps, o);
        if (lane >= o) ps += t;
    }
    if (lane == 31) wsum[w] = ps;
    __syncthreads();
    if (tid == 0) {
        int c = 0;
#pragma unroll
        for (int k = 0; k < 8; k++) { int t = wsum[k]; wsum[k] = c; c += t; }
    }
    __syncthreads();
    int run = boff[blockIdx.x] + wsum[w] + ps - s;  // exclusive prefix at base
#pragma unroll
    for (int k = 0; k < 4; k++) {
        if (base + k < n) off[base + k] = run;
        run += v[k];
    }
}

__global__ void fill_self_kernel(const int* __restrict__ off, int* __restrict__ cursor,
                                 int* __restrict__ csr, int n) {
    int i = blockIdx.x * blockDim.x + threadIdx.x;
    if (i < n) {
        int o = off[i];
        csr[o] = i;
        cursor[i] = o + 1;
    }
}
__global__ void scatter_kernel(const int* __restrict__ src, const int* __restrict__ dst,
                               int* __restrict__ cursor, int* __restrict__ csr, int e) {
    int i = blockIdx.x * blockDim.x + threadIdx.x;
    if (i < e) {
        int p = atomicAdd(&cursor[dst[i]], 1);
        csr[p] = src[i];
    }
}

// ---------------- GAT aggregation: one warp per dst, single fused pass ----------------
// out = (sum_j exp(leaky(as[src_j]+ad[dst])) * hW[src_j]) / sum_j exp(...) + bias
// (identical to max-subtracted softmax; |e| is O(10) so expf is safe in fp32)
__global__ void gat_aggregate_kernel(const int* __restrict__ off, const int* __restrict__ csr,
                                     const float* __restrict__ hW, const float* __restrict__ as_,
                                     const float* __restrict__ ad_, const float* __restrict__ bias,
                                     float* __restrict__ out, int n) {
    int warp = (blockIdx.x * blockDim.x + threadIdx.x) >> 5;
    int lane = threadIdx.x & 31;
    if (warp >= n) return;
    int start = off[warp];
    int end = off[warp + 1];
    float adi = ad_[warp];

    float s = 0.f, acc0 = 0.f, acc1 = 0.f;
    for (int base = start; base < end; base += 32) {
        int j = base + lane;
        int sidx = 0;
        float ex = 0.f;
        if (j < end) {
            sidx = csr[j];
            float e = as_[sidx] + adi;
            e = (e >= 0.f) ? e : 0.2f * e;
            ex = __expf(e);
        }
        s += ex;
        int cnt = min(32, end - base);
        for (int t = 0; t < cnt; t++) {
            int ss = __shfl_sync(0xffffffffu, sidx, t);
            float w = __shfl_sync(0xffffffffu, ex, t);
            float2 v = *(const float2*)(hW + ss * 64 + 2 * lane);
            acc0 += w * v.x;
            acc1 += w * v.y;
        }
    }
#pragma unroll
    for (int o = 16; o; o >>= 1) s += __shfl_xor_sync(0xffffffffu, s, o);
    float inv = 1.f / (s + 1e-16f);

    float2 r;
    r.x = acc0 * inv + bias[2 * lane];
    r.y = acc1 * inv + bias[2 * lane + 1];
    *(float2*)(out + warp * 64 + 2 * lane) = r;
}

// ---------------- host launcher ----------------
static void build_csr(const int* src, const int* dst, int* deg, int* off, int* cursor,
                      int* csr, int* bsum, int* boff) {
    init_deg_kernel<<<(NN + 255) / 256, 256>>>(deg, NN);
    count_kernel<<<(EE + 255) / 256, 256>>>(dst, deg, EE);
    block_sum_kernel<<<NB_SCAN, 256>>>(deg, bsum, NN);
    scan_sums_kernel<<<1, 128>>>(bsum, boff, NB_SCAN, off, NN);
    scan_apply_kernel<<<NB_SCAN, 256>>>(deg, boff, off, NN);
    fill_self_kernel<<<(NN + 255) / 256, 256>>>(off, cursor, csr, NN);
    scatter_kernel<<<(EE + 255) / 256, 256>>>(src, dst, cursor, csr, EE);
}

extern "C" void kernel_launch(void* const* d_in, const int* in_sizes, int n_in,
                              void* d_out, int out_size) {
    const float* x       = (const float*)d_in[0];
    const int*   ei      = (const int*)d_in[1];
    const float* rg_x    = (const float*)d_in[3];
    const int*   rei     = (const int*)d_in[4];
    const float* W1      = (const float*)d_in[6];
    const float* b1      = (const float*)d_in[7];
    const float* atom_W  = (const float*)d_in[8];
    const float* atom_as = (const float*)d_in[9];
    const float* atom_ad = (const float*)d_in[10];
    const float* atom_b  = (const float*)d_in[11];
    const float* rg_W    = (const float*)d_in[12];
    const float* rg_as   = (const float*)d_in[13];
    const float* rg_ad   = (const float*)d_in[14];
    const float* rg_b    = (const float*)d_in[15];
    const float* mol_W   = (const float*)d_in[16];
    const float* mol_as  = (const float*)d_in[17];
    const float* mol_ad  = (const float*)d_in[18];
    const float* mol_b   = (const float*)d_in[19];
    const float* W2      = (const float*)d_in[20];
    const float* b2      = (const float*)d_in[21];
    float* out = (float*)d_out;

    const int* srcA = ei;
    const int* dstA = ei + EE;
    const int* srcR = rei;
    const int* dstR = rei + EE;

    float *h0a, *h0r, *hW, *atomo, *rh, *mol, *as_, *ad_;
    int *degA, *offA, *curA, *csrA, *degR, *offR, *curR, *csrR, *bsum, *boff;
    cudaGetSymbolAddress((void**)&h0a, g_h0a);
    cudaGetSymbolAddress((void**)&h0r, g_h0r);
    cudaGetSymbolAddress((void**)&hW, g_hW);
    cudaGetSymbolAddress((void**)&atomo, g_atom);
    cudaGetSymbolAddress((void**)&rh, g_rh);
    cudaGetSymbolAddress((void**)&mol, g_mol);
    cudaGetSymbolAddress((void**)&as_, g_as);
    cudaGetSymbolAddress((void**)&ad_, g_ad);
    cudaGetSymbolAddress((void**)&degA, g_degA);
    cudaGetSymbolAddress((void**)&offA, g_offA);
    cudaGetSymbolAddress((void**)&curA, g_curA);
    cudaGetSymbolAddress((void**)&csrA, g_csrA);
    cudaGetSymbolAddress((void**)&degR, g_degR);
    cudaGetSymbolAddress((void**)&offR, g_offR);
    cudaGetSymbolAddress((void**)&curR, g_curR);
    cudaGetSymbolAddress((void**)&csrR, g_csrR);
    cudaGetSymbolAddress((void**)&bsum, g_bsum);
    cudaGetSymbolAddress((void**)&boff, g_boff);

    const int GB = (NN + 63) / 64;
    const int WB = (NN * 32 + 255) / 256;

    // lin1 for both graphs (no att fusion)
    gemm64_kernel<<<GB, 256>>>(x, W1, b1, h0a, NN, 0.01f, 1, nullptr, nullptr, nullptr, nullptr);
    gemm64_kernel<<<GB, 256>>>(rg_x, W1, b1, h0r, NN, 0.01f, 1, nullptr, nullptr, nullptr, nullptr);

    // CSR for both graphs
    build_csr(srcA, dstA, degA, offA, curA, csrA, bsum, boff);
    build_csr(srcR, dstR, degR, offR, curR, csrR, bsum, boff);

    // atom conv
    gemm64_kernel<<<GB, 256>>>(h0a, atom_W, nullptr, hW, NN, 0.f, 0, atom_as, atom_ad, as_, ad_);
    gat_aggregate_kernel<<<WB, 256>>>(offA, csrA, hW, as_, ad_, atom_b, atomo, NN);

    // rg conv
    gemm64_kernel<<<GB, 256>>>(h0r, rg_W, nullptr, hW, NN, 0.f, 0, rg_as, rg_ad, as_, ad_);
    gat_aggregate_kernel<<<WB, 256>>>(offR, csrR, hW, as_, ad_, rg_b, rh, NN);

    // mol conv (atom graph, input = atom conv output)
    gemm64_kernel<<<GB, 256>>>(atomo, mol_W, nullptr, hW, NN, 0.f, 0, mol_as, mol_ad, as_, ad_);
    gat_aggregate_kernel<<<WB, 256>>>(offA, csrA, hW, as_, ad_, mol_b, mol, NN);

    // final: out = concat(mol, rh) @ W2 + b2
    gemm_concat_kernel<<<GB, 256>>>(mol, rh, W2, b2, out, NN);
}

// round 5
// speedup vs baseline: 1.7463x; 1.2752x over previous
#include <cuda_runtime.h>
#include <cuda_bf16.h>
#include <math.h>
#include <stdint.h>

#define NN 100000
#define EE 1200000
#define CC 64
#define TOTE (EE + NN)
#define SCHUNK 1024
#define NB_SCAN ((NN + SCHUNK - 1) / SCHUNK)   // 98
#define GEMM_BLOCKS ((NN + 127) / 128)         // 782

// ---------------- scratch (device globals; no allocation allowed) ----------------
__device__ float g_h0a[NN * CC];
__device__ float g_h0r[NN * CC];
__device__ float g_hW[NN * CC];
__device__ float g_hW2[NN * CC];
__device__ float g_atom[NN * CC];
__device__ float g_rh[NN * CC];
__device__ float g_mol[NN * CC];
__device__ float g_as[NN];
__device__ float g_ad[NN];
__device__ float g_as2[NN];
__device__ float g_ad2[NN];

__device__ int g_degA[NN];
__device__ int g_offA[NN + 1];
__device__ int g_curA[NN];
__device__ int g_csrA[TOTE];

__device__ int g_degR[NN];
__device__ int g_offR[NN + 1];
__device__ int g_curR[NN];
__device__ int g_csrR[TOTE];

__device__ int g_bsum[2 * 128];
__device__ int g_boff[2 * 128];

// ================= mma.sync helpers =================
__device__ __forceinline__ uint32_t smem_u32(const void* p) {
    uint32_t a;
    asm("{ .reg .u64 t; cvta.to.shared.u64 t, %1; cvt.u32.u64 %0, t; }" : "=r"(a) : "l"(p));
    return a;
}

#define LDSM_X4(d, addr) asm volatile( \
    "ldmatrix.sync.aligned.m8n8.x4.shared.b16 {%0,%1,%2,%3}, [%4];" \
    : "=r"((d)[0]), "=r"((d)[1]), "=r"((d)[2]), "=r"((d)[3]) : "r"(addr))

#define MMA16816(c, a, b0, b1) asm volatile( \
    "mma.sync.aligned.m16n8k16.row.col.f32.bf16.bf16.f32 " \
    "{%0,%1,%2,%3}, {%4,%5,%6,%7}, {%8,%9}, {%0,%1,%2,%3};" \
    : "+f"((c)[0]), "+f"((c)[1]), "+f"((c)[2]), "+f"((c)[3]) \
    : "r"((a)[0]), "r"((a)[1]), "r"((a)[2]), "r"((a)[3]), "r"(b0), "r"(b1))

// ================= unified tensor-core GEMM =================
// out[r,0:64] = act(sum_ph A_ph[r,0:64] @ W[ph*64:,0:64] + bias)
// optional: as_[r] = out_row . attS ; ad_[r] = out_row . attD
struct TcArgs {
    const float* A;
    const float* A2;      // phase-1 input (concat), else null
    const float* W;       // [K_total, 64] row-major
    const float* bias;
    const float* attS;
    const float* attD;
    float* out;
    float* as_;
    float* ad_;
    int mode;             // 1 bias, 2 leaky(0.01), 4 att, 8 two-phase
};

#define PITCH 136                    // bf16 elems per smem row (272 B, 16B skew)
#define SM_B_OFF (128 * PITCH * 2)   // 34816
#define SM_SC_OFF (SM_B_OFF + 64 * PITCH * 2)  // 52224
#define SM_DYN (SM_SC_OFF + 768)

__global__ void __launch_bounds__(128) mma_gemm_kernel(TcArgs g0, TcArgs g1, int n) {
    extern __shared__ char dsm[];
    __nv_bfloat16* As = (__nv_bfloat16*)dsm;               // [128][PITCH], cols 0-63 hi, 64-127 lo
    __nv_bfloat16* Bs = (__nv_bfloat16*)(dsm + SM_B_OFF);  // [64 n][PITCH k], cols 0-63 hi, 64-127 lo
    float* sc_bias = (float*)(dsm + SM_SC_OFF);
    float* sc_attS = sc_bias + 64;
    float* sc_attD = sc_attS + 64;

    const TcArgs g = blockIdx.y ? g1 : g0;
    int tid = threadIdx.x;
    int w = tid >> 5;
    int lane = tid & 31;
    int row0 = blockIdx.x * 128;

    if (tid < 64) sc_bias[tid] = (g.mode & 1) ? g.bias[tid] : 0.f;
    else if (g.mode & 4) { sc_attS[tid - 64] = g.attS[tid - 64]; sc_attD[tid - 64] = g.attD[tid - 64]; }

    float acc[2][8][4];
#pragma unroll
    for (int mi = 0; mi < 2; mi++)
#pragma unroll
        for (int ni = 0; ni < 8; ni++)
#pragma unroll
            for (int k = 0; k < 4; k++) acc[mi][ni][k] = 0.f;

    uint32_t As_u = smem_u32(As);
    uint32_t Bs_u = smem_u32(Bs);

    // per-lane ldmatrix base offsets
    // A (.x4, tiles: m0-7/k0, m8-15/k0, m0-7/k8, m8-15/k8)
    int a_row_local = lane & 15;               // row within m16 tile
    int a_kofs = (lane >> 4) * 8;              // 0 or 8
    // B (.x4, tiles: n0-7/k0, n0-7/k8, n8-15/k0, n8-15/k8)
    int b_n = (lane & 7) + ((lane >> 4) & 1) * 8;
    int b_kofs = ((lane >> 3) & 1) * 8;

    // 12 K16 steps covering hi*hi, lo*hi, hi*lo (lo*lo omitted, ~2^-18)
    const int AK[12] = {0, 16, 32, 48, 64, 80, 96, 112, 0, 16, 32, 48};
    const int BK[12] = {0, 16, 32, 48, 0, 16, 32, 48, 64, 80, 96, 112};

    int nphase = (g.mode & 8) ? 2 : 1;
    for (int ph = 0; ph < nphase; ph++) {
        const float* Asrc = ph ? g.A2 : g.A;
        const float* Wsrc = g.W + ph * 64 * 64;
        if (ph) __syncthreads();

        // convert A: fp32 [128x64] -> bf16 hi(0:64) | lo(64:128)
        for (int i = tid; i < 128 * 64; i += 128) {
            int r = i >> 6, c = i & 63;
            int gr = row0 + r;
            float v = (gr < n) ? Asrc[gr * 64 + c] : 0.f;
            __nv_bfloat16 h = __float2bfloat16(v);
            As[r * PITCH + c] = h;
            As[r * PITCH + 64 + c] = __float2bfloat16(v - __bfloat162float(h));
        }
        // convert B: Bs[n][k] = hi(W[k][n]); Bs[n][64+k] = lo(W[k][n])
        for (int i = tid; i < 64 * 64; i += 128) {
            int k = i >> 6, nn = i & 63;
            float v = Wsrc[i];
            __nv_bfloat16 h = __float2bfloat16(v);
            Bs[nn * PITCH + k] = h;
            Bs[nn * PITCH + 64 + k] = __float2bfloat16(v - __bfloat162float(h));
        }
        __syncthreads();

        uint32_t a_addr0 = As_u + ((w * 32 + 0 * 16 + a_row_local) * PITCH + a_kofs) * 2;
        uint32_t a_addr1 = As_u + ((w * 32 + 1 * 16 + a_row_local) * PITCH + a_kofs) * 2;
        uint32_t b_base = Bs_u + (b_n * PITCH + b_kofs) * 2;

#pragma unroll
        for (int s = 0; s < 12; s++) {
            uint32_t a_koff = AK[s] * 2;
            uint32_t b_koff = BK[s] * 2;
            uint32_t a0[4], a1[4];
            LDSM_X4(a0, a_addr0 + a_koff);
            LDSM_X4(a1, a_addr1 + a_koff);
#pragma unroll
            for (int nb = 0; nb < 4; nb++) {
                uint32_t b[4];
                LDSM_X4(b, b_base + (nb * 16 * PITCH) * 2 + b_koff);
                MMA16816(acc[0][nb * 2 + 0], a0, b[0], b[1]);
                MMA16816(acc[0][nb * 2 + 1], a0, b[2], b[3]);
                MMA16816(acc[1][nb * 2 + 0], a1, b[0], b[1]);
                MMA16816(acc[1][nb * 2 + 1], a1, b[2], b[3]);
            }
        }
    }

    // ---- epilogue straight from fragments ----
    int q = lane & 3;       // quad index -> column pair
    int rsub = lane >> 2;   // 0..7
#pragma unroll
    for (int mi = 0; mi < 2; mi++) {
#pragma unroll
        for (int half = 0; half < 2; half++) {
            int r = row0 + w * 32 + mi * 16 + rsub + half * 8;
            float s = 0.f, d = 0.f;
#pragma unroll
            for (int ni = 0; ni < 8; ni++) {
                int c = ni * 8 + q * 2;
                float v0 = acc[mi][ni][half * 2 + 0] + sc_bias[c];
                float v1 = acc[mi][ni][half * 2 + 1] + sc_bias[c + 1];
                if (g.mode & 2) {
                    v0 = (v0 >= 0.f) ? v0 : 0.01f * v0;
                    v1 = (v1 >= 0.f) ? v1 : 0.01f * v1;
                }
                if (g.mode & 4) {
                    s += v0 * sc_attS[c] + v1 * sc_attS[c + 1];
                    d += v0 * sc_attD[c] + v1 * sc_attD[c + 1];
                }
                if (r < n) {
                    float2 st = {v0, v1};
                    *(float2*)(g.out + r * 64 + c) = st;
                }
            }
            if (g.mode & 4) {
                s += __shfl_xor_sync(0xffffffffu, s, 1);
                s += __shfl_xor_sync(0xffffffffu, s, 2);
                d += __shfl_xor_sync(0xffffffffu, d, 1);
                d += __shfl_xor_sync(0xffffffffu, d, 2);
                if (q == 0 && r < n) { g.as_[r] = s; g.ad_[r] = d; }
            }
        }
    }
}

// ================= CSR build (merged: blockIdx.y selects graph) =================
__global__ void init_deg_kernel(int* degA, int* degR) {
    int i = blockIdx.x * blockDim.x + threadIdx.x;
    int* deg = blockIdx.y ? degR : degA;
    if (i < NN) deg[i] = 1;  // self loop
}
__global__ void count_kernel(const int* dstA, const int* dstR, int* degA, int* degR) {
    int i = blockIdx.x * blockDim.x + threadIdx.x;
    const int* dst = blockIdx.y ? dstR : dstA;
    int* deg = blockIdx.y ? degR : degA;
    if (i < EE) atomicAdd(&deg[dst[i]], 1);
}
__global__ void block_sum_kernel(const int* degA, const int* degR, int* bsum) {
    __shared__ int sh[8];
    const int* deg = blockIdx.y ? degR : degA;
    int base = blockIdx.x * SCHUNK;
    int tid = threadIdx.x;
    int s = 0;
    for (int i = tid; i < SCHUNK; i += 256) {
        int idx = base + i;
        if (idx < NN) s += deg[idx];
    }
#pragma unroll
    for (int o = 16; o; o >>= 1) s += __shfl_xor_sync(0xffffffffu, s, o);
    if ((tid & 31) == 0) sh[tid >> 5] = s;
    __syncthreads();
    if (tid == 0) {
        int t = 0;
#pragma unroll
        for (int k = 0; k < 8; k++) t += sh[k];
        bsum[blockIdx.y * 128 + blockIdx.x] = t;
    }
}
__global__ void scan_sums_kernel(const int* bsum, int* boff, int* offA, int* offR) {
    __shared__ int sh[128];
    int y = blockIdx.x;
    int tid = threadIdx.x;
    int v = (tid < NB_SCAN) ? bsum[y * 128 + tid] : 0;
    sh[tid] = v;
    __syncthreads();
    for (int o = 1; o < 128; o <<= 1) {
        int t = (tid >= o) ? sh[tid - o] : 0;
        __syncthreads();
        sh[tid] += t;
        __syncthreads();
    }
    if (tid < NB_SCAN) boff[y * 128 + tid] = sh[tid] - v;
    if (tid == 127) (y ? offR : offA)[NN] = sh[127];
}
__global__ void scan_apply_kernel(const int* degA, const int* degR, const int* boff,
                                  int* offA, int* offR) {
    __shared__ int wsum[8];
    const int* deg = blockIdx.y ? degR : degA;
    int* off = blockIdx.y ? offR : offA;
    int tid = threadIdx.x;
    int lane = tid & 31, w = tid >> 5;
    int base = blockIdx.x * SCHUNK + tid * 4;
    int v[4];
    int s = 0;
#pragma unroll
    for (int k = 0; k < 4; k++) {
        v[k] = (base + k < NN) ? deg[base + k] : 0;
        s += v[k];
    }
    int ps = s;
#pragma unroll
    for (int o = 1; o < 32; o <<= 1) {
        int t = __shfl_up_sync(0xffffffffu, ps, o);
        if (lane >= o) ps += t;
    }
    if (lane == 31) wsum[w] = ps;
    __syncthreads();
    if (tid == 0) {
        int c = 0;
#pragma unroll
        for (int k = 0; k < 8; k++) { int t = wsum[k]; wsum[k] = c; c += t; }
    }
    __syncthreads();
    int run = boff[blockIdx.y * 128 + blockIdx.x] + wsum[w] + ps - s;
#pragma unroll
    for (int k = 0; k < 4; k++) {
        if (base + k < NN) off[base + k] = run;
        run += v[k];
    }
}
__global__ void fill_self_kernel(const int* offA, const int* offR, int* curA, int* curR,
                                 int* csrA, int* csrR) {
    int i = blockIdx.x * blockDim.x + threadIdx.x;
    const int* off = blockIdx.y ? offR : offA;
    int* cursor = blockIdx.y ? curR : curA;
    int* csr = blockIdx.y ? csrR : csrA;
    if (i < NN) {
        int o = off[i];
        csr[o] = i;
        cursor[i] = o + 1;
    }
}
__global__ void scatter_kernel(const int* srcA, const int* dstA, const int* srcR, const int* dstR,
                               int* curA, int* curR, int* csrA, int* csrR) {
    int i = blockIdx.x * blockDim.x + threadIdx.x;
    const int* src = blockIdx.y ? srcR : srcA;
    const int* dst = blockIdx.y ? dstR : dstA;
    int* cursor = blockIdx.y ? curR : curA;
    int* csr = blockIdx.y ? csrR : csrA;
    if (i < EE) {
        int p = atomicAdd(&cursor[dst[i]], 1);
        csr[p] = src[i];
    }
}

// ================= GAT aggregation (merged via blockIdx.y) =================
struct AggArgs {
    const int* off;
    const int* csr;
    const float* hW;
    const float* as_;
    const float* ad_;
    const float* bias;
    float* out;
};
__global__ void gat_aggregate_kernel(AggArgs a0, AggArgs a1) {
    const AggArgs a = blockIdx.y ? a1 : a0;
    int warp = (blockIdx.x * blockDim.x + threadIdx.x) >> 5;
    int lane = threadIdx.x & 31;
    if (warp >= NN) return;
    int start = a.off[warp];
    int end = a.off[warp + 1];
    float adi = a.ad_[warp];

    float s = 0.f, acc0 = 0.f, acc1 = 0.f;
    for (int base = start; base < end; base += 32) {
        int j = base + lane;
        int sidx = 0;
        float ex = 0.f;
        if (j < end) {
            sidx = a.csr[j];
            float e = a.as_[sidx] + adi;
            e = (e >= 0.f) ? e : 0.2f * e;
            ex = __expf(e);
        }
        s += ex;
        int cnt = min(32, end - base);
        for (int t = 0; t < cnt; t++) {
            int ss = __shfl_sync(0xffffffffu, sidx, t);
            float w = __shfl_sync(0xffffffffu, ex, t);
            float2 v = *(const float2*)(a.hW + ss * 64 + 2 * lane);
            acc0 += w * v.x;
            acc1 += w * v.y;
        }
    }
#pragma unroll
    for (int o = 16; o; o >>= 1) s += __shfl_xor_sync(0xffffffffu, s, o);
    float inv = 1.f / (s + 1e-16f);

    float2 r;
    r.x = acc0 * inv + a.bias[2 * lane];
    r.y = acc1 * inv + a.bias[2 * lane + 1];
    *(float2*)(a.out + warp * 64 + 2 * lane) = r;
}

// ================= host launcher =================
extern "C" void kernel_launch(void* const* d_in, const int* in_sizes, int n_in,
                              void* d_out, int out_size) {
    const float* x       = (const float*)d_in[0];
    const int*   ei      = (const int*)d_in[1];
    const float* rg_x    = (const float*)d_in[3];
    const int*   rei     = (const int*)d_in[4];
    const float* W1      = (const float*)d_in[6];
    const float* b1      = (const float*)d_in[7];
    const float* atom_W  = (const float*)d_in[8];
    const float* atom_as = (const float*)d_in[9];
    const float* atom_ad = (const float*)d_in[10];
    const float* atom_b  = (const float*)d_in[11];
    const float* rg_W    = (const float*)d_in[12];
    const float* rg_as   = (const float*)d_in[13];
    const float* rg_ad   = (const float*)d_in[14];
    const float* rg_b    = (const float*)d_in[15];
    const float* mol_W   = (const float*)d_in[16];
    const float* mol_as  = (const float*)d_in[17];
    const float* mol_ad  = (const float*)d_in[18];
    const float* mol_b   = (const float*)d_in[19];
    const float* W2      = (const float*)d_in[20];
    const float* b2      = (const float*)d_in[21];
    float* out = (float*)d_out;

    const int* srcA = ei;
    const int* dstA = ei + EE;
    const int* srcR = rei;
    const int* dstR = rei + EE;

    float *h0a, *h0r, *hW, *hW2, *atomo, *rh, *mol, *as_, *ad_, *as2, *ad2;
    int *degA, *offA, *curA, *csrA, *degR, *offR, *curR, *csrR, *bsum, *boff;
    cudaGetSymbolAddress((void**)&h0a, g_h0a);
    cudaGetSymbolAddress((void**)&h0r, g_h0r);
    cudaGetSymbolAddress((void**)&hW, g_hW);
    cudaGetSymbolAddress((void**)&hW2, g_hW2);
    cudaGetSymbolAddress((void**)&atomo, g_atom);
    cudaGetSymbolAddress((void**)&rh, g_rh);
    cudaGetSymbolAddress((void**)&mol, g_mol);
    cudaGetSymbolAddress((void**)&as_, g_as);
    cudaGetSymbolAddress((void**)&ad_, g_ad);
    cudaGetSymbolAddress((void**)&as2, g_as2);
    cudaGetSymbolAddress((void**)&ad2, g_ad2);
    cudaGetSymbolAddress((void**)&degA, g_degA);
    cudaGetSymbolAddress((void**)&offA, g_offA);
    cudaGetSymbolAddress((void**)&curA, g_curA);
    cudaGetSymbolAddress((void**)&csrA, g_csrA);
    cudaGetSymbolAddress((void**)&degR, g_degR);
    cudaGetSymbolAddress((void**)&offR, g_offR);
    cudaGetSymbolAddress((void**)&curR, g_curR);
    cudaGetSymbolAddress((void**)&csrR, g_csrR);
    cudaGetSymbolAddress((void**)&bsum, g_bsum);
    cudaGetSymbolAddress((void**)&boff, g_boff);

    cudaFuncSetAttribute(mma_gemm_kernel, cudaFuncAttributeMaxDynamicSharedMemorySize, SM_DYN);

    const int WB = (NN * 32 + 255) / 256;

    // CSR build, both graphs per launch
    init_deg_kernel<<<dim3((NN + 255) / 256, 2), 256>>>(degA, degR);
    count_kernel<<<dim3((EE + 255) / 256, 2), 256>>>(dstA, dstR, degA, degR);
    block_sum_kernel<<<dim3(NB_SCAN, 2), 256>>>(degA, degR, bsum);
    scan_sums_kernel<<<2, 128>>>(bsum, boff, offA, offR);
    scan_apply_kernel<<<dim3(NB_SCAN, 2), 256>>>(degA, degR, boff, offA, offR);
    fill_self_kernel<<<dim3((NN + 255) / 256, 2), 256>>>(offA, offR, curA, curR, csrA, csrR);
    scatter_kernel<<<dim3((EE + 255) / 256, 2), 256>>>(srcA, dstA, srcR, dstR, curA, curR, csrA, csrR);

    // lin1 both graphs: mode = bias | act
    TcArgs l0 = {x,    nullptr, W1, b1, nullptr, nullptr, h0a, nullptr, nullptr, 3};
    TcArgs l1 = {rg_x, nullptr, W1, b1, nullptr, nullptr, h0r, nullptr, nullptr, 3};
    mma_gemm_kernel<<<dim3(GEMM_BLOCKS, 2), 128, SM_DYN>>>(l0, l1, NN);

    // atom + rg conv gemm (mode = att)
    TcArgs c0 = {h0a, nullptr, atom_W, nullptr, atom_as, atom_ad, hW,  as_, ad_, 4};
    TcArgs c1 = {h0r, nullptr, rg_W,   nullptr, rg_as,   rg_ad,   hW2, as2, ad2, 4};
    mma_gemm_kernel<<<dim3(GEMM_BLOCKS, 2), 128, SM_DYN>>>(c0, c1, NN);

    // atom + rg aggregation
    AggArgs a0 = {offA, csrA, hW,  as_, ad_, atom_b, atomo};
    AggArgs a1 = {offR, csrR, hW2, as2, ad2, rg_b,   rh};
    gat_aggregate_kernel<<<dim3(WB, 2), 256>>>(a0, a1);

    // mol conv gemm
    TcArgs m0 = {atomo, nullptr, mol_W, nullptr, mol_as, mol_ad, hW, as_, ad_, 4};
    mma_gemm_kernel<<<dim3(GEMM_BLOCKS, 1), 128, SM_DYN>>>(m0, m0, NN);

    // mol aggregation
    AggArgs am = {offA, csrA, hW, as_, ad_, mol_b, mol};
    gat_aggregate_kernel<<<dim3(WB, 1), 256>>>(am, am);

    // final concat gemm: two-phase, bias
    TcArgs f0 = {mol, rh, W2, b2, nullptr, nullptr, out, nullptr, nullptr, 1 | 8};
    mma_gemm_kernel<<<dim3(GEMM_BLOCKS, 1), 128, SM_DYN>>>(f0, f0, NN);
}